// round 3
// baseline (speedup 1.0000x reference)
#include <cuda_runtime.h>
#include <cstdint>
#include <cstddef>

// ---------------- problem constants (fixed shapes for this problem) ----------
#define H      256
#define HV     (H/4)          // float4 groups per row = 64
#define L_CONV 4
#define CDIM   16
#define N_MAX  50176          // 392*128, >= 50000
#define E_MAX  800000
#define HCAT   ((L_CONV+1)*H) // 1280
#define SBLK   512            // stats partial blocks

// ---------------- device scratch (static; no runtime allocation) -------------
__device__ float  g_hcat[(size_t)N_MAX * HCAT];   // [h0|h1|h2|h3|h4]
__device__ float  g_agg [(size_t)N_MAX * H];      // agg; later reused as readout act
__device__ float  g_z1  [(size_t)N_MAX * H];
__device__ int    g_deg [N_MAX];
__device__ int    g_rowptr[N_MAX + 1];
__device__ int    g_cursor[N_MAX];
__device__ int    g_colidx[E_MAX];
__device__ float  g_cnt [N_MAX];                  // 1 + in-degree
__device__ float  g_gamma[L_CONV * H], g_beta[L_CONV * H];
__device__ float  g_ps [SBLK * H];                // per-block partial sums
__device__ float  g_ps2[SBLK * H];                // per-block partial sumsq
__device__ float  g_scale[H], g_sbias[H];
__device__ int    g_bsum[256], g_boff[256];

// ---------------- tiny kernels ----------------------------------------------

// NOTE: `state` is int32 on device. The reference requests jnp.int64, but JAX
// with default x64-disabled config silently produces int32. Reading it as
// int64 fused adjacent elements into wild 64-bit indices -> addresses in the
// shared aperture -> device fault 717. Read as int32.
__global__ void k_embed(const int* __restrict__ state,
                        const float* __restrict__ emb, int N) {
    int idx = blockIdx.x * blockDim.x + threadIdx.x;
    if (idx >= N * HV) return;
    int n = idx >> 6, q = idx & 63;
    int s = state[n];
    float4 v = reinterpret_cast<const float4*>(emb)[s * HV + q];
    reinterpret_cast<float4*>(g_hcat + (size_t)n * HCAT)[q] = v;
}

__global__ void k_film(const float* __restrict__ c,
                       const float* __restrict__ fW,
                       const float* __restrict__ fb) {
    int t = blockIdx.x * blockDim.x + threadIdx.x;
    if (t >= L_CONV * 2 * H) return;
    int i = t / (2 * H), o = t % (2 * H);
    float acc = fb[i * 2 * H + o];
    #pragma unroll
    for (int k = 0; k < CDIM; k++)
        acc = fmaf(c[k], fW[(i * CDIM + k) * 2 * H + o], acc);
    if (o < H) g_gamma[i * H + o] = acc;
    else       g_beta [i * H + o - H] = acc;
}

__global__ void k_zero_deg(int N) {
    int i = blockIdx.x * blockDim.x + threadIdx.x;
    if (i < N) g_deg[i] = 0;
}

__global__ void k_hist(const int* __restrict__ dst, int E) {
    int e = blockIdx.x * blockDim.x + threadIdx.x;
    if (e < E) atomicAdd(&g_deg[dst[e]], 1);
}

__global__ void k_scan1(int N) {
    __shared__ int sh[256];
    int t = threadIdx.x;
    int i = blockIdx.x * 256 + t;
    int d = (i < N) ? g_deg[i] : 0;
    sh[t] = d;
    __syncthreads();
    #pragma unroll
    for (int o = 1; o < 256; o <<= 1) {
        int x = (t >= o) ? sh[t - o] : 0;
        __syncthreads();
        sh[t] += x;
        __syncthreads();
    }
    if (i < N) {
        g_rowptr[i + 1] = sh[t];
        g_cursor[i] = 0;
        g_cnt[i] = 1.0f + (float)d;
    }
    if (t == 255) g_bsum[blockIdx.x] = sh[255];
    if (i == 0)   g_rowptr[0] = 0;
}

__global__ void k_scan2(int nch) {
    __shared__ int sh[256];
    int t = threadIdx.x;
    int v = (t < nch) ? g_bsum[t] : 0;
    sh[t] = v;
    __syncthreads();
    #pragma unroll
    for (int o = 1; o < 256; o <<= 1) {
        int x = (t >= o) ? sh[t - o] : 0;
        __syncthreads();
        sh[t] += x;
        __syncthreads();
    }
    if (t < nch) g_boff[t] = sh[t] - v;   // exclusive offsets
}

__global__ void k_scan3(int N) {
    int i = blockIdx.x * blockDim.x + threadIdx.x;
    if (i < N) g_rowptr[i + 1] += g_boff[i >> 8];
}

__global__ void k_fill(const int* __restrict__ src,
                       const int* __restrict__ dst, int E) {
    int e = blockIdx.x * blockDim.x + threadIdx.x;
    if (e >= E) return;
    int d = dst[e];
    int p = g_rowptr[d] + atomicAdd(&g_cursor[d], 1);
    g_colidx[p] = src[e];
}

// agg[n] = sum over edges (dst==n) of h[src]   (raw h, FiLM folded into GEMM)
__global__ void k_gather(int off, int N) {
    int tid = threadIdx.x;
    int n = blockIdx.x * 4 + (tid >> 6);
    if (n >= N) return;
    int q = tid & 63;
    int p0 = g_rowptr[n], p1 = g_rowptr[n + 1];
    float4 acc = make_float4(0.f, 0.f, 0.f, 0.f);
    for (int p = p0; p < p1; p++) {
        int s = g_colidx[p];
        float4 v = reinterpret_cast<const float4*>(g_hcat + (size_t)s * HCAT + off)[q];
        acc.x += v.x; acc.y += v.y; acc.z += v.z; acc.w += v.w;
    }
    reinterpret_cast<float4*>(g_agg + (size_t)n * H)[q] = acc;
}

// per-column partial sum/sumsq (fp32, plain stores; no atomics)
// zsel: 0 -> g_z1 (ld H); 1 -> g_hcat + zoff (ld HCAT)
__global__ void k_stats(int zsel, int zoff, int N) {
    const float* z  = zsel ? (g_hcat + zoff) : g_z1;
    const int    ld = zsel ? HCAT : H;
    int col = threadIdx.x;
    float s = 0.f, s2 = 0.f;
    for (int r = blockIdx.x; r < N; r += SBLK) {
        float v = z[(size_t)r * ld + col];
        s  += v;
        s2 += v * v;
    }
    g_ps [blockIdx.x * H + col] = s;
    g_ps2[blockIdx.x * H + col] = s2;
}

// reduce partials (fp64 registers, no atomics) -> scale/sbias
__global__ void k_bnp(const float* __restrict__ g,
                      const float* __restrict__ b, int N) {
    int c = threadIdx.x;
    double s = 0.0, s2 = 0.0;
    for (int p = 0; p < SBLK; p++) {
        s  += (double)g_ps [p * H + c];
        s2 += (double)g_ps2[p * H + c];
    }
    double m   = s  / (double)N;
    double var = s2 / (double)N - m * m;
    double sc  = (double)g[c] / sqrt(var + 1e-5);
    g_scale[c] = (float)sc;
    g_sbias[c] = (float)((double)b[c] - m * sc);
}

// hcat slot (layer+1) = relu(bn2(raw z2)) in place
__global__ void k_finish(int layer, int N) {
    int idx = blockIdx.x * blockDim.x + threadIdx.x;
    if (idx >= N * HV) return;
    int n = idx >> 6, q = idx & 63;
    float4* slot = reinterpret_cast<float4*>(g_hcat + (size_t)n * HCAT + (layer + 1) * H);
    float4 v = slot[q];
    int k = q * 4;
    float4 o;
    o.x = fmaxf(fmaf(v.x, g_scale[k + 0], g_sbias[k + 0]), 0.f);
    o.y = fmaxf(fmaf(v.y, g_scale[k + 1], g_sbias[k + 1]), 0.f);
    o.z = fmaxf(fmaf(v.z, g_scale[k + 2], g_sbias[k + 2]), 0.f);
    o.w = fmaxf(fmaf(v.w, g_scale[k + 3], g_sbias[k + 3]), 0.f);
    slot[q] = o;
}

// out[n, 0..1] = act[n,:] @ ro_W2 + ro_b2  (one warp per row; act lives in g_agg)
__global__ void k_out(const float* __restrict__ W2,
                      const float* __restrict__ b2,
                      float* __restrict__ out, int N) {
    int gtid = blockIdx.x * blockDim.x + threadIdx.x;
    int w = gtid >> 5, lane = gtid & 31;
    if (w >= N) return;
    const float* row = g_agg + (size_t)w * H;
    float a0 = 0.f, a1 = 0.f;
    for (int k = lane; k < H; k += 32) {
        float v = row[k];
        a0 = fmaf(v, W2[2 * k + 0], a0);
        a1 = fmaf(v, W2[2 * k + 1], a1);
    }
    #pragma unroll
    for (int o = 16; o > 0; o >>= 1) {
        a0 += __shfl_xor_sync(0xffffffffu, a0, o);
        a1 += __shfl_xor_sync(0xffffffffu, a1, o);
    }
    if (lane == 0) {
        out[2 * w + 0] = a0 + b2[0];
        out[2 * w + 1] = a1 + b2[1];
    }
}

// ---------------- SGEMM: 128x128 tile, BK=16, 8x8 per thread -----------------
// amode: 0 = plain A
//        1 = relu(A*scale[k] + sbias[k])            (fused BN+ReLU on input)
//        2 = gamma[k]*(A + agg) + cnt[row]*beta[k]  (fused FiLM + self + agg)
// asel : 0 = g_hcat + aoff (lda=HCAT), 1 = g_z1 (lda=H)
// csel : 0 = g_z1 (ldc H), 1 = g_hcat + coff (ldc HCAT), 2 = g_agg (ldc H)
// epi  : 0 = plain store, 1 = relu(acc + ebias[col])
#define BM 128
#define BN 128
#define BK 16

__global__ void __launch_bounds__(256, 2)
k_sgemm(int asel, int aoff, int amode, int layer,
        const float* __restrict__ B, int ldb,
        int csel, int coff, const float* __restrict__ ebias, int epi,
        int M, int K) {
    __shared__ __align__(16) float As[BK][BM + 4];
    __shared__ __align__(16) float Bs[BK][BN];

    const float* A  = (asel == 0) ? (g_hcat + aoff) : g_z1;
    const int    lda = (asel == 0) ? HCAT : H;
    float*       C  = (csel == 0) ? g_z1 : (csel == 1 ? (g_hcat + coff) : g_agg);
    const int    ldc = (csel == 1) ? HCAT : H;
    const float* t0 = (amode == 2) ? (g_gamma + layer * H) : g_scale;
    const float* t1 = (amode == 2) ? (g_beta  + layer * H) : g_sbias;

    const int tid   = threadIdx.x;
    const int rtile = blockIdx.y * BM;
    const int ctile = blockIdx.x * BN;
    const int a_row = tid >> 2;
    const int a_kq  = (tid & 3) << 2;
    const int b_kr  = tid >> 5;
    const int b_c   = (tid & 31) << 2;
    const int ty    = tid >> 4, tx = tid & 15;

    float4 rA[2], rB[2];
    float  acc[8][8];
    #pragma unroll
    for (int i = 0; i < 8; i++)
        #pragma unroll
        for (int j = 0; j < 8; j++) acc[i][j] = 0.f;

    float cn[2] = {0.f, 0.f};
    if (amode == 2) {
        #pragma unroll
        for (int j = 0; j < 2; j++) {
            int row = rtile + a_row + j * 64;
            cn[j] = (row < M) ? g_cnt[row] : 0.f;
        }
    }

    auto loadA = [&](int kk) {
        #pragma unroll
        for (int j = 0; j < 2; j++) {
            int row = rtile + a_row + j * 64;
            int kg  = kk + a_kq;
            float4 v = make_float4(0.f, 0.f, 0.f, 0.f);
            if (row < M) {
                v = *reinterpret_cast<const float4*>(A + (size_t)row * lda + kg);
                if (amode == 1) {
                    float4 s  = *reinterpret_cast<const float4*>(t0 + kg);
                    float4 bb = *reinterpret_cast<const float4*>(t1 + kg);
                    v.x = fmaxf(fmaf(v.x, s.x, bb.x), 0.f);
                    v.y = fmaxf(fmaf(v.y, s.y, bb.y), 0.f);
                    v.z = fmaxf(fmaf(v.z, s.z, bb.z), 0.f);
                    v.w = fmaxf(fmaf(v.w, s.w, bb.w), 0.f);
                } else if (amode == 2) {
                    float4 g4 = *reinterpret_cast<const float4*>(t0 + kg);
                    float4 b4 = *reinterpret_cast<const float4*>(t1 + kg);
                    float4 w  = *reinterpret_cast<const float4*>(g_agg + (size_t)row * H + kg);
                    float  c0 = cn[j];
                    v.x = fmaf(g4.x, v.x + w.x, c0 * b4.x);
                    v.y = fmaf(g4.y, v.y + w.y, c0 * b4.y);
                    v.z = fmaf(g4.z, v.z + w.z, c0 * b4.z);
                    v.w = fmaf(g4.w, v.w + w.w, c0 * b4.w);
                }
            }
            rA[j] = v;
        }
    };
    auto storeA = [&]() {
        #pragma unroll
        for (int j = 0; j < 2; j++) {
            As[a_kq + 0][a_row + j * 64] = rA[j].x;
            As[a_kq + 1][a_row + j * 64] = rA[j].y;
            As[a_kq + 2][a_row + j * 64] = rA[j].z;
            As[a_kq + 3][a_row + j * 64] = rA[j].w;
        }
    };
    auto loadB = [&](int kk) {
        #pragma unroll
        for (int j = 0; j < 2; j++) {
            int kr = kk + b_kr + j * 8;
            rB[j] = *reinterpret_cast<const float4*>(B + (size_t)kr * ldb + ctile + b_c);
        }
    };
    auto storeB = [&]() {
        #pragma unroll
        for (int j = 0; j < 2; j++)
            *reinterpret_cast<float4*>(&Bs[b_kr + j * 8][b_c]) = rB[j];
    };
    auto compute = [&]() {
        #pragma unroll
        for (int k = 0; k < BK; k++) {
            float a[8], b[8];
            *reinterpret_cast<float4*>(&a[0]) = *reinterpret_cast<const float4*>(&As[k][ty * 8]);
            *reinterpret_cast<float4*>(&a[4]) = *reinterpret_cast<const float4*>(&As[k][ty * 8 + 4]);
            *reinterpret_cast<float4*>(&b[0]) = *reinterpret_cast<const float4*>(&Bs[k][tx * 8]);
            *reinterpret_cast<float4*>(&b[4]) = *reinterpret_cast<const float4*>(&Bs[k][tx * 8 + 4]);
            #pragma unroll
            for (int i = 0; i < 8; i++)
                #pragma unroll
                for (int j = 0; j < 8; j++)
                    acc[i][j] = fmaf(a[i], b[j], acc[i][j]);
        }
    };

    loadA(0); loadB(0);
    storeA(); storeB();
    __syncthreads();
    for (int kk = BK; kk < K; kk += BK) {
        loadA(kk); loadB(kk);
        compute();
        __syncthreads();
        storeA(); storeB();
        __syncthreads();
    }
    compute();

    #pragma unroll
    for (int i = 0; i < 8; i++) {
        int row = rtile + ty * 8 + i;
        if (row >= M) continue;
        #pragma unroll
        for (int j = 0; j < 8; j += 4) {
            int col = ctile + tx * 8 + j;
            float4 o;
            o.x = acc[i][j + 0]; o.y = acc[i][j + 1];
            o.z = acc[i][j + 2]; o.w = acc[i][j + 3];
            if (epi == 1) {
                o.x = fmaxf(o.x + ebias[col + 0], 0.f);
                o.y = fmaxf(o.y + ebias[col + 1], 0.f);
                o.z = fmaxf(o.z + ebias[col + 2], 0.f);
                o.w = fmaxf(o.w + ebias[col + 3], 0.f);
            }
            *reinterpret_cast<float4*>(C + (size_t)row * ldc + col) = o;
        }
    }
}

// ---------------- launcher ---------------------------------------------------
extern "C" void kernel_launch(void* const* d_in, const int* in_sizes, int n_in,
                              void* d_out, int out_size) {
    const int*   state  = (const int*)  d_in[0];   // int32 on device (JAX x64 off)
    const int*   src    = (const int*)  d_in[1];
    const int*   dst    = (const int*)  d_in[2];
    const float* c      = (const float*)d_in[3];
    const float* emb    = (const float*)d_in[4];
    const float* film_W = (const float*)d_in[5];
    const float* film_b = (const float*)d_in[6];
    const float* W1     = (const float*)d_in[7];
    const float* bn1_g  = (const float*)d_in[8];
    const float* bn1_b  = (const float*)d_in[9];
    const float* W2     = (const float*)d_in[10];
    const float* bn2_g  = (const float*)d_in[11];
    const float* bn2_b  = (const float*)d_in[12];
    const float* ro_W1  = (const float*)d_in[13];
    const float* ro_b1  = (const float*)d_in[14];
    const float* ro_W2  = (const float*)d_in[15];
    const float* ro_b2  = (const float*)d_in[16];
    float* out = (float*)d_out;

    const int N = in_sizes[0];
    const int E = in_sizes[1];

    // node embedding -> hcat[:, 0:H]
    k_embed<<<(N * HV + 255) / 256, 256>>>(state, emb, N);
    // all layers' FiLM gamma/beta
    k_film<<<(L_CONV * 2 * H + 255) / 256, 256>>>(c, film_W, film_b);

    // CSR build (once per launch; topology shared by all layers)
    k_zero_deg<<<(N + 255) / 256, 256>>>(N);
    k_hist<<<(E + 255) / 256, 256>>>(dst, E);
    int chunks = (N + 255) / 256;
    k_scan1<<<chunks, 256>>>(N);
    k_scan2<<<1, 256>>>(chunks);
    k_scan3<<<(N + 255) / 256, 256>>>(N);
    k_fill<<<(E + 255) / 256, 256>>>(src, dst, E);

    dim3 ggrid(H / BN, (N + BM - 1) / BM);

    for (int i = 0; i < L_CONV; i++) {
        // agg = segment_sum of raw h (FiLM folded into GEMM1's A-transform)
        k_gather<<<(N + 3) / 4, 256>>>(i * H, N);
        // z1 = [gamma*(h+agg) + cnt*beta] @ W1[i]
        k_sgemm<<<ggrid, 256>>>(0, i * H, 2, i, W1 + (size_t)i * H * H, H,
                                0, 0, ro_b1, 0, N, H);
        k_stats<<<SBLK, 256>>>(0, 0, N);
        k_bnp<<<1, 256>>>(bn1_g + i * H, bn1_b + i * H, N);
        // raw z2 = relu(bn1(z1)) @ W2[i]  -> hcat slot (i+1)
        k_sgemm<<<ggrid, 256>>>(1, 0, 1, i, W2 + (size_t)i * H * H, H,
                                1, (i + 1) * H, ro_b1, 0, N, H);
        k_stats<<<SBLK, 256>>>(1, (i + 1) * H, N);
        k_bnp<<<1, 256>>>(bn2_g + i * H, bn2_b + i * H, N);
        // hcat slot (i+1) = relu(bn2(z2)) in place
        k_finish<<<(N * HV + 255) / 256, 256>>>(i, N);
    }

    // act = relu(hcat @ ro_W1 + ro_b1) -> g_agg (reuse)
    k_sgemm<<<ggrid, 256>>>(0, 0, 0, 0, ro_W1, H, 2, 0, ro_b1, 1, N, HCAT);
    // out = act @ ro_W2 + ro_b2
    k_out<<<(N * 32 + 255) / 256, 256>>>(ro_W2, ro_b2, out, N);
}

// round 10
// speedup vs baseline: 1.1212x; 1.1212x over previous
#include <cuda_runtime.h>
#include <cstdint>
#include <cstddef>

// ---------------- problem constants (fixed shapes for this problem) ----------
#define H      256
#define HV     (H/4)          // float4 groups per row = 64
#define L_CONV 4
#define CDIM   16
#define N_MAX  50176          // 392*128, >= 50000
#define E_MAX  800000
#define HCAT   ((L_CONV+1)*H) // 1280
#define SBLK   512            // stats partial blocks

// ---------------- device scratch (static; no runtime allocation) -------------
// NOTE: g_* symbols are referenced ONLY inside device code. Passing them as
// host-side kernel arguments (rounds 4-9) resolved to the host shadow symbol
// and triggered a 128MiB managed-migration allocation -> harness rule
// violation. All buffer selection is via integer flags resolved in-kernel.
__device__ float    g_hcat[(size_t)N_MAX * HCAT];   // [h0|h1|h2|h3|h4]
__device__ float    g_agg [(size_t)N_MAX * H];      // agg; later readout act
__device__ float    g_z1  [(size_t)N_MAX * H];
__device__ int      g_deg [N_MAX];
__device__ int      g_rowptr[N_MAX + 1];
__device__ int      g_cursor[N_MAX];
__device__ int      g_colidx[E_MAX];
__device__ float    g_cnt [N_MAX];                  // 1 + in-degree
__device__ float    g_gamma[L_CONV * H], g_beta[L_CONV * H];
__device__ float    g_ps [SBLK * H];
__device__ float    g_ps2[SBLK * H];
__device__ float    g_scale[H], g_sbias[H];
__device__ int      g_bsum[256], g_boff[256];
__device__ float    g_rotab[3 * H];                 // emb @ ro_W1[0:H,:]
// tf32 hi/lo weight splits
__device__ uint32_t g_w1h[L_CONV * H * H], g_w1l[L_CONV * H * H];
__device__ uint32_t g_w2h[L_CONV * H * H], g_w2l[L_CONV * H * H];
__device__ uint32_t g_roh[HCAT * H],       g_rol[HCAT * H];

// ---------------- tf32 helpers ----------------------------------------------
__device__ __forceinline__ uint32_t f2tf32(float v) {
    uint32_t r;
    asm("cvt.rna.tf32.f32 %0, %1;" : "=r"(r) : "f"(v));
    return r;
}
__device__ __forceinline__ void tf32_split(float v, uint32_t& h, uint32_t& l) {
    h = f2tf32(v);
    l = f2tf32(v - __uint_as_float(h));
}

#define MMA_TF32(c, a0_, a1_, a2_, a3_, b0_, b1_)                           \
    asm volatile(                                                           \
        "mma.sync.aligned.m16n8k8.row.col.f32.tf32.tf32.f32 "               \
        "{%0,%1,%2,%3}, {%4,%5,%6,%7}, {%8,%9}, {%0,%1,%2,%3};"             \
        : "+f"((c)[0]), "+f"((c)[1]), "+f"((c)[2]), "+f"((c)[3])            \
        : "r"(a0_), "r"(a1_), "r"(a2_), "r"(a3_),                           \
          "r"(b0_), "r"(b1_))

// ---------------- tiny kernels ----------------------------------------------

// state is int32 on device (JAX x64 disabled downgrades int64 silently).
__global__ void k_embed(const int* __restrict__ state,
                        const float* __restrict__ emb, int N) {
    int idx = blockIdx.x * blockDim.x + threadIdx.x;
    if (idx >= N * HV) return;
    int n = idx >> 6, q = idx & 63;
    int s = state[n];
    float4 v = reinterpret_cast<const float4*>(emb)[s * HV + q];
    reinterpret_cast<float4*>(g_hcat + (size_t)n * HCAT)[q] = v;
}

__global__ void k_film(const float* __restrict__ c,
                       const float* __restrict__ fW,
                       const float* __restrict__ fb) {
    int t = blockIdx.x * blockDim.x + threadIdx.x;
    if (t >= L_CONV * 2 * H) return;
    int i = t / (2 * H), o = t % (2 * H);
    float acc = fb[i * 2 * H + o];
    #pragma unroll
    for (int k = 0; k < CDIM; k++)
        acc = fmaf(c[k], fW[(i * CDIM + k) * 2 * H + o], acc);
    if (o < H) g_gamma[i * H + o] = acc;
    else       g_beta [i * H + o - H] = acc;
}

// fp32 -> tf32 hi/lo split. Destination selected DEVICE-SIDE by dsel.
__global__ void k_split(const float* __restrict__ src, int dsel, int n) {
    int i = blockIdx.x * blockDim.x + threadIdx.x;
    if (i >= n) return;
    uint32_t* h = (dsel == 0) ? g_w1h : (dsel == 1) ? g_w2h : g_roh;
    uint32_t* l = (dsel == 0) ? g_w1l : (dsel == 1) ? g_w2l : g_rol;
    float v = src[i];
    uint32_t hb = f2tf32(v);
    h[i] = hb;
    l[i] = f2tf32(v - __uint_as_float(hb));
}

// rotab[s][c] = sum_k emb[s,k] * ro_W1[k,c]  (3 x 256 table)
__global__ void k_rotab(const float* __restrict__ emb,
                        const float* __restrict__ roW1) {
    int s = blockIdx.x, c = threadIdx.x;
    float acc = 0.f;
    for (int k = 0; k < H; k++)
        acc = fmaf(emb[s * H + k], roW1[k * H + c], acc);
    g_rotab[s * H + c] = acc;
}

__global__ void k_zero_deg(int N) {
    int i = blockIdx.x * blockDim.x + threadIdx.x;
    if (i < N) g_deg[i] = 0;
}

__global__ void k_hist(const int* __restrict__ dst, int E) {
    int e = blockIdx.x * blockDim.x + threadIdx.x;
    if (e < E) atomicAdd(&g_deg[dst[e]], 1);
}

__global__ void k_scan1(int N) {
    __shared__ int sh[256];
    int t = threadIdx.x;
    int i = blockIdx.x * 256 + t;
    int d = (i < N) ? g_deg[i] : 0;
    sh[t] = d;
    __syncthreads();
    #pragma unroll
    for (int o = 1; o < 256; o <<= 1) {
        int x = (t >= o) ? sh[t - o] : 0;
        __syncthreads();
        sh[t] += x;
        __syncthreads();
    }
    if (i < N) {
        g_rowptr[i + 1] = sh[t];
        g_cursor[i] = 0;
        g_cnt[i] = 1.0f + (float)d;
    }
    if (t == 255) g_bsum[blockIdx.x] = sh[255];
    if (i == 0)   g_rowptr[0] = 0;
}

__global__ void k_scan2(int nch) {
    __shared__ int sh[256];
    int t = threadIdx.x;
    int v = (t < nch) ? g_bsum[t] : 0;
    sh[t] = v;
    __syncthreads();
    #pragma unroll
    for (int o = 1; o < 256; o <<= 1) {
        int x = (t >= o) ? sh[t - o] : 0;
        __syncthreads();
        sh[t] += x;
        __syncthreads();
    }
    if (t < nch) g_boff[t] = sh[t] - v;
}

__global__ void k_scan3(int N) {
    int i = blockIdx.x * blockDim.x + threadIdx.x;
    if (i < N) g_rowptr[i + 1] += g_boff[i >> 8];
}

__global__ void k_fill(const int* __restrict__ src,
                       const int* __restrict__ dst, int E) {
    int e = blockIdx.x * blockDim.x + threadIdx.x;
    if (e >= E) return;
    int d = dst[e];
    int p = g_rowptr[d] + atomicAdd(&g_cursor[d], 1);
    g_colidx[p] = src[e];
}

// agg[n] = sum over edges (dst==n) of h[src]
__global__ void k_gather(int off, int N) {
    int tid = threadIdx.x;
    int n = blockIdx.x * 4 + (tid >> 6);
    if (n >= N) return;
    int q = tid & 63;
    int p0 = g_rowptr[n], p1 = g_rowptr[n + 1];
    float4 acc = make_float4(0.f, 0.f, 0.f, 0.f);
    for (int p = p0; p < p1; p++) {
        int s = g_colidx[p];
        float4 v = reinterpret_cast<const float4*>(g_hcat + (size_t)s * HCAT + off)[q];
        acc.x += v.x; acc.y += v.y; acc.z += v.z; acc.w += v.w;
    }
    reinterpret_cast<float4*>(g_agg + (size_t)n * H)[q] = acc;
}

// per-column partial sum/sumsq
__global__ void k_stats(int zsel, int zoff, int N) {
    const float* z  = zsel ? (g_hcat + zoff) : g_z1;
    const int    ld = zsel ? HCAT : H;
    int col = threadIdx.x;
    float s = 0.f, s2 = 0.f;
    for (int r = blockIdx.x; r < N; r += SBLK) {
        float v = z[(size_t)r * ld + col];
        s  += v;
        s2 += v * v;
    }
    g_ps [blockIdx.x * H + col] = s;
    g_ps2[blockIdx.x * H + col] = s2;
}

__global__ void k_bnp(const float* __restrict__ g,
                      const float* __restrict__ b, int N) {
    int c = threadIdx.x;
    double s = 0.0, s2 = 0.0;
    for (int p = 0; p < SBLK; p++) {
        s  += (double)g_ps [p * H + c];
        s2 += (double)g_ps2[p * H + c];
    }
    double m   = s  / (double)N;
    double var = s2 / (double)N - m * m;
    double sc  = (double)g[c] / sqrt(var + 1e-5);
    g_scale[c] = (float)sc;
    g_sbias[c] = (float)((double)b[c] - m * sc);
}

// hcat slot (layer+1) = relu(bn2(raw z2)) in place
__global__ void k_finish(int layer, int N) {
    int idx = blockIdx.x * blockDim.x + threadIdx.x;
    if (idx >= N * HV) return;
    int n = idx >> 6, q = idx & 63;
    float4* slot = reinterpret_cast<float4*>(g_hcat + (size_t)n * HCAT + (layer + 1) * H);
    float4 v = slot[q];
    int k = q * 4;
    float4 o;
    o.x = fmaxf(fmaf(v.x, g_scale[k + 0], g_sbias[k + 0]), 0.f);
    o.y = fmaxf(fmaf(v.y, g_scale[k + 1], g_sbias[k + 1]), 0.f);
    o.z = fmaxf(fmaf(v.z, g_scale[k + 2], g_sbias[k + 2]), 0.f);
    o.w = fmaxf(fmaf(v.w, g_scale[k + 3], g_sbias[k + 3]), 0.f);
    slot[q] = o;
}

// out[n, 0..1] = act[n,:] @ ro_W2 + ro_b2  (act in g_agg)
__global__ void k_out(const float* __restrict__ W2,
                      const float* __restrict__ b2,
                      float* __restrict__ out, int N) {
    int gtid = blockIdx.x * blockDim.x + threadIdx.x;
    int w = gtid >> 5, lane = gtid & 31;
    if (w >= N) return;
    const float* row = g_agg + (size_t)w * H;
    float a0 = 0.f, a1 = 0.f;
    for (int k = lane; k < H; k += 32) {
        float v = row[k];
        a0 = fmaf(v, W2[2 * k + 0], a0);
        a1 = fmaf(v, W2[2 * k + 1], a1);
    }
    #pragma unroll
    for (int o = 16; o > 0; o >>= 1) {
        a0 += __shfl_xor_sync(0xffffffffu, a0, o);
        a1 += __shfl_xor_sync(0xffffffffu, a1, o);
    }
    if (lane == 0) {
        out[2 * w + 0] = a0 + b2[0];
        out[2 * w + 1] = a1 + b2[1];
    }
}

// ---------------- 3xTF32 tensor-core GEMM -----------------------------------
// C = A' @ B as Ah@Bh + Ah@Bl + Al@Bh with tf32 mma (error ~2^-22).
// Tile BM=128 BN=128 BK=16; 8 warps (4m x 2n), warp tile 32x64.
// Weight buffers selected DEVICE-SIDE (wsel/woff) -- no symbol args.
// amode: 0 plain; 1 relu(A*scale+sbias); 2 gamma*(A+agg)+cnt*beta
// asel : 0 g_hcat+aoff (lda HCAT), 1 g_z1 (lda H)
// csel : 0 g_z1 (ldc H), 1 g_hcat+coff (ldc HCAT), 2 g_agg (ldc H)
// epi  : 0 plain, 1 relu(acc+ebias), 2 relu(acc+ebias+rotab[state[row]])
#define BM 128
#define BN 128
#define BK 16

__global__ void __launch_bounds__(256)
k_mma(int asel, int aoff, int amode, int layer,
      int wsel, int woff, int ldb,
      int csel, int coff, const float* __restrict__ ebias, int epi,
      const int* __restrict__ statep, int M, int K) {
    __shared__ __align__(16) uint32_t As[2][BM][20];
    __shared__ __align__(16) uint32_t Bs[2][BK][136];

    const uint32_t* Bh = ((wsel == 0) ? g_w1h : (wsel == 1) ? g_w2h : g_roh) + woff;
    const uint32_t* Bl = ((wsel == 0) ? g_w1l : (wsel == 1) ? g_w2l : g_rol) + woff;
    const float* A   = (asel == 0) ? (g_hcat + aoff) : g_z1;
    const int    lda = (asel == 0) ? HCAT : H;
    float*       C   = (csel == 0) ? g_z1 : (csel == 1 ? (g_hcat + coff) : g_agg);
    const int    ldc = (csel == 1) ? HCAT : H;
    const float* t0  = (amode == 2) ? (g_gamma + layer * H) : g_scale;
    const float* t1  = (amode == 2) ? (g_beta  + layer * H) : g_sbias;

    const int tid   = threadIdx.x;
    const int rtile = blockIdx.y * BM;
    const int ctile = blockIdx.x * BN;
    const int warp  = tid >> 5, lane = tid & 31;
    const int gid   = lane >> 2, tig = lane & 3;
    const int wm    = (warp & 3) * 32;
    const int wn    = (warp >> 2) * 64;

    float Cr[2][8][4];
    #pragma unroll
    for (int mt = 0; mt < 2; mt++)
        #pragma unroll
        for (int nt = 0; nt < 8; nt++)
            #pragma unroll
            for (int r = 0; r < 4; r++) Cr[mt][nt][r] = 0.f;

    for (int kk = 0; kk < K; kk += BK) {
        __syncthreads();
        // A: gmem -> transform -> split -> smem (2 float4 per thread)
        #pragma unroll
        for (int j = 0; j < 2; j++) {
            int idx = tid + j * 256;
            int row = idx >> 2, q = idx & 3;
            int grow = rtile + row;
            int kg   = kk + q * 4;
            float4 v = make_float4(0.f, 0.f, 0.f, 0.f);
            if (grow < M) {
                v = *reinterpret_cast<const float4*>(A + (size_t)grow * lda + kg);
                if (amode == 1) {
                    float4 s  = *reinterpret_cast<const float4*>(t0 + kg);
                    float4 bb = *reinterpret_cast<const float4*>(t1 + kg);
                    v.x = fmaxf(fmaf(v.x, s.x, bb.x), 0.f);
                    v.y = fmaxf(fmaf(v.y, s.y, bb.y), 0.f);
                    v.z = fmaxf(fmaf(v.z, s.z, bb.z), 0.f);
                    v.w = fmaxf(fmaf(v.w, s.w, bb.w), 0.f);
                } else if (amode == 2) {
                    float4 g4 = *reinterpret_cast<const float4*>(t0 + kg);
                    float4 b4 = *reinterpret_cast<const float4*>(t1 + kg);
                    float4 w  = *reinterpret_cast<const float4*>(g_agg + (size_t)grow * H + kg);
                    float  c0 = g_cnt[grow];
                    v.x = fmaf(g4.x, v.x + w.x, c0 * b4.x);
                    v.y = fmaf(g4.y, v.y + w.y, c0 * b4.y);
                    v.z = fmaf(g4.z, v.z + w.z, c0 * b4.z);
                    v.w = fmaf(g4.w, v.w + w.w, c0 * b4.w);
                }
            }
            uint4 hi, lo;
            tf32_split(v.x, hi.x, lo.x);
            tf32_split(v.y, hi.y, lo.y);
            tf32_split(v.z, hi.z, lo.z);
            tf32_split(v.w, hi.w, lo.w);
            *reinterpret_cast<uint4*>(&As[0][row][q * 4]) = hi;
            *reinterpret_cast<uint4*>(&As[1][row][q * 4]) = lo;
        }
        // B: gmem -> smem (2 uint4 hi + 2 uint4 lo per thread)
        #pragma unroll
        for (int j = 0; j < 2; j++) {
            int idx = tid + j * 256;
            int kb  = idx >> 5;
            int n4  = (idx & 31) << 2;
            size_t off = (size_t)(kk + kb) * ldb + ctile + n4;
            *reinterpret_cast<uint4*>(&Bs[0][kb][n4]) =
                *reinterpret_cast<const uint4*>(Bh + off);
            *reinterpret_cast<uint4*>(&Bs[1][kb][n4]) =
                *reinterpret_cast<const uint4*>(Bl + off);
        }
        __syncthreads();
        // compute: 2 k-steps of 8; JIT B fragments
        #pragma unroll
        for (int s = 0; s < 2; s++) {
            const int k0 = s * 8;
            uint32_t ah[2][4], al[2][4];
            #pragma unroll
            for (int mt = 0; mt < 2; mt++) {
                int r0 = wm + mt * 16 + gid;
                ah[mt][0] = As[0][r0    ][k0 + tig];
                ah[mt][1] = As[0][r0 + 8][k0 + tig];
                ah[mt][2] = As[0][r0    ][k0 + tig + 4];
                ah[mt][3] = As[0][r0 + 8][k0 + tig + 4];
                al[mt][0] = As[1][r0    ][k0 + tig];
                al[mt][1] = As[1][r0 + 8][k0 + tig];
                al[mt][2] = As[1][r0    ][k0 + tig + 4];
                al[mt][3] = As[1][r0 + 8][k0 + tig + 4];
            }
            #pragma unroll
            for (int nt = 0; nt < 8; nt++) {
                int n0 = wn + nt * 8 + gid;
                uint32_t b0h = Bs[0][k0 + tig    ][n0];
                uint32_t b1h = Bs[0][k0 + tig + 4][n0];
                uint32_t b0l = Bs[1][k0 + tig    ][n0];
                uint32_t b1l = Bs[1][k0 + tig + 4][n0];
                MMA_TF32(Cr[0][nt], ah[0][0], ah[0][1], ah[0][2], ah[0][3], b0h, b1h);
                MMA_TF32(Cr[1][nt], ah[1][0], ah[1][1], ah[1][2], ah[1][3], b0h, b1h);
                MMA_TF32(Cr[0][nt], ah[0][0], ah[0][1], ah[0][2], ah[0][3], b0l, b1l);
                MMA_TF32(Cr[1][nt], ah[1][0], ah[1][1], ah[1][2], ah[1][3], b0l, b1l);
                MMA_TF32(Cr[0][nt], al[0][0], al[0][1], al[0][2], al[0][3], b0h, b1h);
                MMA_TF32(Cr[1][nt], al[1][0], al[1][1], al[1][2], al[1][3], b0h, b1h);
            }
        }
    }

    // epilogue
    #pragma unroll
    for (int mt = 0; mt < 2; mt++) {
        int r0 = rtile + wm + mt * 16 + gid;
        int r1 = r0 + 8;
        const float* tab0 = g_rotab;
        const float* tab1 = g_rotab;
        if (epi == 2) {
            if (r0 < M) tab0 = g_rotab + statep[r0] * H;
            if (r1 < M) tab1 = g_rotab + statep[r1] * H;
        }
        #pragma unroll
        for (int nt = 0; nt < 8; nt++) {
            int col = ctile + wn + nt * 8 + tig * 2;
            float2 v0 = make_float2(Cr[mt][nt][0], Cr[mt][nt][1]);
            float2 v1 = make_float2(Cr[mt][nt][2], Cr[mt][nt][3]);
            if (epi == 1) {
                float e0 = ebias[col], e1 = ebias[col + 1];
                v0.x = fmaxf(v0.x + e0, 0.f); v0.y = fmaxf(v0.y + e1, 0.f);
                v1.x = fmaxf(v1.x + e0, 0.f); v1.y = fmaxf(v1.y + e1, 0.f);
            } else if (epi == 2) {
                float e0 = ebias[col], e1 = ebias[col + 1];
                v0.x = fmaxf(v0.x + e0 + tab0[col], 0.f);
                v0.y = fmaxf(v0.y + e1 + tab0[col + 1], 0.f);
                v1.x = fmaxf(v1.x + e0 + tab1[col], 0.f);
                v1.y = fmaxf(v1.y + e1 + tab1[col + 1], 0.f);
            }
            if (r0 < M) *reinterpret_cast<float2*>(C + (size_t)r0 * ldc + col) = v0;
            if (r1 < M) *reinterpret_cast<float2*>(C + (size_t)r1 * ldc + col) = v1;
        }
    }
}

// ---------------- launcher ---------------------------------------------------
extern "C" void kernel_launch(void* const* d_in, const int* in_sizes, int n_in,
                              void* d_out, int out_size) {
    const int*   state  = (const int*)  d_in[0];
    const int*   src    = (const int*)  d_in[1];
    const int*   dst    = (const int*)  d_in[2];
    const float* c      = (const float*)d_in[3];
    const float* emb    = (const float*)d_in[4];
    const float* film_W = (const float*)d_in[5];
    const float* film_b = (const float*)d_in[6];
    const float* W1     = (const float*)d_in[7];
    const float* bn1_g  = (const float*)d_in[8];
    const float* bn1_b  = (const float*)d_in[9];
    const float* W2     = (const float*)d_in[10];
    const float* bn2_g  = (const float*)d_in[11];
    const float* bn2_b  = (const float*)d_in[12];
    const float* ro_W1  = (const float*)d_in[13];
    const float* ro_b1  = (const float*)d_in[14];
    const float* ro_W2  = (const float*)d_in[15];
    const float* ro_b2  = (const float*)d_in[16];
    float* out = (float*)d_out;

    const int N = in_sizes[0];
    const int E = in_sizes[1];

    k_embed<<<(N * HV + 255) / 256, 256>>>(state, emb, N);
    k_film<<<(L_CONV * 2 * H + 255) / 256, 256>>>(c, film_W, film_b);
    k_rotab<<<3, 256>>>(emb, ro_W1);

    // weight tf32 hi/lo splits (device-side destination selection)
    {
        int n1 = L_CONV * H * H;
        k_split<<<(n1 + 255) / 256, 256>>>(W1, 0, n1);
        k_split<<<(n1 + 255) / 256, 256>>>(W2, 1, n1);
        int n2 = HCAT * H;
        k_split<<<(n2 + 255) / 256, 256>>>(ro_W1, 2, n2);
    }

    // CSR build (once per launch)
    k_zero_deg<<<(N + 255) / 256, 256>>>(N);
    k_hist<<<(E + 255) / 256, 256>>>(dst, E);
    int chunks = (N + 255) / 256;
    k_scan1<<<chunks, 256>>>(N);
    k_scan2<<<1, 256>>>(chunks);
    k_scan3<<<(N + 255) / 256, 256>>>(N);
    k_fill<<<(E + 255) / 256, 256>>>(src, dst, E);

    dim3 ggrid(H / BN, (N + BM - 1) / BM);

    for (int i = 0; i < L_CONV; i++) {
        k_gather<<<(N + 3) / 4, 256>>>(i * H, N);
        // z1 = [gamma*(h+agg) + cnt*beta] @ W1[i]
        k_mma<<<ggrid, 256>>>(0, i * H, 2, i, 0, i * H * H, H,
                              0, 0, ro_b1, 0, state, N, H);
        k_stats<<<SBLK, 256>>>(0, 0, N);
        k_bnp<<<1, 256>>>(bn1_g + i * H, bn1_b + i * H, N);
        // raw z2 = relu(bn1(z1)) @ W2[i] -> hcat slot (i+1)
        k_mma<<<ggrid, 256>>>(1, 0, 1, i, 1, i * H * H, H,
                              1, (i + 1) * H, ro_b1, 0, state, N, H);
        k_stats<<<SBLK, 256>>>(1, (i + 1) * H, N);
        k_bnp<<<1, 256>>>(bn2_g + i * H, bn2_b + i * H, N);
        k_finish<<<(N * HV + 255) / 256, 256>>>(i, N);
    }

    // act = relu(hcat[:,H:] @ ro_W1[H:,:] + rotab[state] + ro_b1) -> g_agg
    // (emb contribution via 3-row table; K reduced 1280 -> 1024)
    k_mma<<<ggrid, 256>>>(0, H, 0, 0, 2, H * H, H,
                          2, 0, ro_b1, 2, state, N, HCAT - H);
    // out = act @ ro_W2 + ro_b2
    k_out<<<(N * 32 + 255) / 256, 256>>>(ro_W2, ro_b2, out, N);
}